// round 11
// baseline (speedup 1.0000x reference)
#include <cuda_runtime.h>
#include <cstdint>

// Problem constants
#define B_ 32
#define T_ 1024
#define D_ 256
#define H_ 256
#define NS 32                      // items per batch: 1024 items x 32 t-rows

// Scratch (allocation-free rule: __device__ globals)
__device__ float g_part[B_ * NS * D_];   // 1 MB of partial t-sums
__device__ float g_W[B_ * D_];
__device__ float g_bv[B_ * D_];

__device__ __forceinline__ float4 add4(float4 a, float4 b)
{
    return make_float4(a.x + b.x, a.y + b.y, a.z + b.z, a.w + b.w);
}

// ---------------------------------------------------------------------------
// Kernel 1: partial t-sums. grid 1024, block 256. (best measured shape: R6)
// Item w = 32 consecutive t-rows. Thread (tx in [0,64): d4, ty in [0,4)):
// 8 front-batched independent LDG.128.
// Triggers downstream launch IMMEDIATELY (dependents self-guard via sync).
// ---------------------------------------------------------------------------
__global__ void __launch_bounds__(256) k_reduce(const float* __restrict__ x)
{
    cudaTriggerProgrammaticLaunchCompletion();   // let mlp/out launch now

    const int w  = blockIdx.x;
    const int tx = threadIdx.x & 63;
    const int ty = threadIdx.x >> 6;

    const float4* xp = reinterpret_cast<const float4*>(x) + (size_t)w * (32 * 64);

    float4 v[8];
#pragma unroll
    for (int k = 0; k < 8; k++)
        v[k] = xp[(ty + 4 * k) * 64 + tx];

    float4 s0 = add4(add4(v[0], v[1]), add4(v[2], v[3]));
    float4 s1 = add4(add4(v[4], v[5]), add4(v[6], v[7]));
    float4 acc = add4(s0, s1);

    __shared__ float4 sm[4][64];
    sm[ty][tx] = acc;
    __syncthreads();
    if (ty == 0) {
        float4 r = add4(add4(sm[0][tx], sm[1][tx]), add4(sm[2][tx], sm[3][tx]));
        reinterpret_cast<float4*>(g_part)[w * 64 + tx] = r;
    }
}

// ---------------------------------------------------------------------------
// Kernel 2: the two MLPs. grid (B, 2), block 256.
// Pre-sync: launches immediately (reduce triggers at entry), warms all
// 1 MB of weights into L2 while reduce streams x. Then syncs and computes.
// Triggers k_out's launch immediately as well.
// ---------------------------------------------------------------------------
__global__ void __launch_bounds__(256) k_mlp(
    const int* __restrict__ len,
    const float* __restrict__ w1w, const float* __restrict__ w1b,
    const float* __restrict__ w2w, const float* __restrict__ w2b,
    const float* __restrict__ v1w, const float* __restrict__ v1b,
    const float* __restrict__ v2w, const float* __restrict__ v2b)
{
    cudaTriggerProgrammaticLaunchCompletion();   // let k_out launch now

    const int b   = blockIdx.x;
    const int sel = blockIdx.y;
    const float* W1 = sel ? v1w : w1w;
    const float* B1 = sel ? v1b : w1b;
    const float* W2 = sel ? v2w : w2w;
    const float* B2 = sel ? v2b : w2b;

    const int j = threadIdx.x;

    // ---- pre-sync: warm the 4 weight matrices (4 x 2048 lines of 128B) ----
    {
        const int ctaid = b * 2 + sel;               // 0..63
        const int idx   = ctaid * 128 + (j >> 1);    // 8192 lines total, 2 thr/line
        const int mat   = idx >> 11;                 // 0..3
        const int line  = idx & 2047;
        const float* bases[4] = { w1w, w2w, v1w, v2w };
        const char* p = (const char*)bases[mat] + (size_t)line * 128;
        asm volatile("prefetch.global.L2 [%0];" :: "l"(p));
    }

    cudaGridDependencySynchronize();   // wait for k_reduce results

    __shared__ float c[D_];
    __shared__ float h[H_];

    // finalize mean (partials L2-resident)
    {
        float s = 0.f;
#pragma unroll
        for (int p = 0; p < NS; p++)
            s += g_part[(b * NS + p) * D_ + j];
        c[j] = s / (float)__ldg(&len[b]);
    }
    __syncthreads();

    // layer 1
    {
        const float4* row = reinterpret_cast<const float4*>(W1 + (size_t)j * D_);
        const float4* cv  = reinterpret_cast<const float4*>(c);
        float acc = B1[j];
#pragma unroll 8
        for (int i = 0; i < D_ / 4; i++) {
            float4 w = row[i], cc = cv[i];
            acc += w.x * cc.x + w.y * cc.y + w.z * cc.z + w.w * cc.w;
        }
        h[j] = 0.5f * acc * (1.f + erff(acc * 0.70710678118654752f));  // exact gelu
    }
    __syncthreads();

    // layer 2
    {
        const float4* row = reinterpret_cast<const float4*>(W2 + (size_t)j * H_);
        const float4* hv  = reinterpret_cast<const float4*>(h);
        float acc = B2[j];
#pragma unroll 8
        for (int i = 0; i < H_ / 4; i++) {
            float4 w = row[i], hh = hv[i];
            acc += w.x * hh.x + w.y * hh.y + w.z * hh.z + w.w * hh.w;
        }
        (sel ? g_bv : g_W)[b * D_ + j] = acc;
    }
}

// ---------------------------------------------------------------------------
// Kernel 3: elementwise output, warp-per-row.
// Launches while reduce/mlp still run (both trigger at entry). Pre-sync:
//  - valid rows (t < L): load x into registers (L2-shared with reduce)
//  - invalid rows:        store zeros (no mlp dependency) -> done early
// Post-sync: multiply by (1+W), add bv at t==0, store.
// ---------------------------------------------------------------------------
__global__ void __launch_bounds__(256) k_out(
    const float* __restrict__ x,
    const int* __restrict__ len,
    float* __restrict__ out)
{
    const int w    = threadIdx.x >> 5;
    const int lane = threadIdx.x & 31;
    const int row  = blockIdx.x * 8 + w;      // b*T + t
    const int t = row & (T_ - 1);
    const int b = row >> 10;

    const size_t i0 = (size_t)row * 64 + lane;
    const float4* x4 = reinterpret_cast<const float4*>(x);
    float4*       o4 = reinterpret_cast<float4*>(out);

    const int L = __ldg(&len[b]);
    const bool valid = (t < L);

    float4 xa, xb;
    if (valid) {                 // pre-sync: x/len independent of upstream
        xa = x4[i0];
        xb = x4[i0 + 32];
    } else {                     // pre-sync: zero rows have no dependency
        float4 z = make_float4(0.f, 0.f, 0.f, 0.f);
        o4[i0]      = z;
        o4[i0 + 32] = z;
    }

    cudaGridDependencySynchronize();   // wait for g_W / g_bv

    if (valid) {
        float4 wa = reinterpret_cast<const float4*>(g_W)[b * 64 + lane];
        float4 wb = reinterpret_cast<const float4*>(g_W)[b * 64 + lane + 32];
        float4 va, vb;
        va.x = (1.f + wa.x) * xa.x;  va.y = (1.f + wa.y) * xa.y;
        va.z = (1.f + wa.z) * xa.z;  va.w = (1.f + wa.w) * xa.w;
        vb.x = (1.f + wb.x) * xb.x;  vb.y = (1.f + wb.y) * xb.y;
        vb.z = (1.f + wb.z) * xb.z;  vb.w = (1.f + wb.w) * xb.w;
        if (t == 0) {
            float4 ba = reinterpret_cast<const float4*>(g_bv)[b * 64 + lane];
            float4 bb = reinterpret_cast<const float4*>(g_bv)[b * 64 + lane + 32];
            va = add4(va, ba);
            vb = add4(vb, bb);
        }
        o4[i0]      = va;
        o4[i0 + 32] = vb;
    }
}

// ---------------------------------------------------------------------------
extern "C" void kernel_launch(void* const* d_in, const int* in_sizes, int n_in,
                              void* d_out, int out_size)
{
    const float* x    = (const float*)d_in[0];
    const int*   len  = (const int*)  d_in[1];
    const float* w1w  = (const float*)d_in[2];
    const float* w1b  = (const float*)d_in[3];
    const float* w2w  = (const float*)d_in[4];
    const float* w2b  = (const float*)d_in[5];
    const float* v1w  = (const float*)d_in[6];
    const float* v1b  = (const float*)d_in[7];
    const float* v2w  = (const float*)d_in[8];
    const float* v2b  = (const float*)d_in[9];
    float* out = (float*)d_out;

    // Kernel 1: normal launch
    k_reduce<<<B_ * NS, 256>>>(x);

    // PDL attribute for the two dependent kernels
    cudaLaunchAttribute pdl;
    pdl.id = cudaLaunchAttributeProgrammaticStreamSerialization;
    pdl.val.programmaticStreamSerializationAllowed = 1;

    // Kernel 2: mlp (PDL secondary of k_reduce; launches at reduce's entry)
    {
        cudaLaunchConfig_t cfg = {};
        cfg.gridDim  = dim3(B_, 2);
        cfg.blockDim = dim3(256);
        cfg.attrs    = &pdl;
        cfg.numAttrs = 1;
        cudaLaunchKernelEx(&cfg, k_mlp, len, w1w, w1b, w2w, w2b,
                           v1w, v1b, v2w, v2b);
    }

    // Kernel 3: out (PDL secondary of k_mlp; launches at mlp's entry)
    {
        cudaLaunchConfig_t cfg = {};
        cfg.gridDim  = dim3(B_ * T_ / 8);
        cfg.blockDim = dim3(256);
        cfg.attrs    = &pdl;
        cfg.numAttrs = 1;
        cudaLaunchKernelEx(&cfg, k_out, x, len, out);
    }
}